// round 11
// baseline (speedup 1.0000x reference)
#include <cuda_runtime.h>
#include <math.h>

#define DDIM 2048
#define DEPTH 9
#define BM 128
#define BN 128
#define BK 16
#define TM 8
#define TN 8
#define NCHUNK 4
#define TILES_PER_CHUNK 32              // (DDIM/NCHUNK)/BK
#define NTILES (DDIM / BK)              // 128

#define AS_ROW (BM + 4)                 // 132 floats
#define BS_ROW (BN + 4)                 // 132 floats
#define TILE_A_BYTES (BK * AS_ROW * 4)  // 8448
#define TILE_B_BYTES (BK * BS_ROW * 4)  // 8448
#define SMEM_SUM_OFF (2 * (TILE_A_BYTES + TILE_B_BYTES))   // 33792
#define SMEM_TOTAL (SMEM_SUM_OFF + 256 * (TN / 2) * TM * 8) // +65536 = 99328

typedef unsigned long long u64;

// Packed fp32x2 ops (Blackwell FFMA2 path). Each 32-bit lane gets IEEE fp32 .rn
// rounding identical to scalar fmaf/add — bit-exact per element.
#define FMA_F32X2(d, a, b, c) \
    asm("fma.rn.f32x2 %0, %1, %2, %3;" : "=l"(d) : "l"(a), "l"(b), "l"(c))
#define ADD_F32X2_(d, a, b) \
    asm("add.rn.f32x2 %0, %1, %2;" : "=l"(d) : "l"(a), "l"(b))
#define PACK_F32X2_(out, lo, hi) \
    asm("mov.b64 %0, {%1, %2};" : "=l"(out) : "f"(lo), "f"(hi))
#define UNPACK_F32X2_(lo, hi, in) \
    asm("mov.b64 {%0, %1}, %2;" : "=f"(lo), "=f"(hi) : "l"(in))

// Scratch (no allocation allowed) — ping-pong activation buffers + u vectors.
__device__ float g_buf0[(size_t)DDIM * DDIM];
__device__ float g_buf1[(size_t)DDIM * DDIM];
__device__ float g_u1[DDIM];
__device__ float g_u2[DDIM];

// u[j] = (1/n) * (prod_{d,g} cos(uw[d, j, g]))^2   (closed form of _ultimate)
__global__ void ultimate_u_kernel(const float* __restrict__ uw, float* __restrict__ u) {
    int j = blockIdx.x * blockDim.x + threadIdx.x;
    if (j >= DDIM) return;
    float p = 1.0f;
#pragma unroll
    for (int d = 0; d < DEPTH; d++) {
        size_t base = (size_t)d * DDIM * DDIM + (size_t)j * DDIM;
        p *= cosf(uw[base + 0]);
        p *= cosf(uw[base + 1]);
        p *= cosf(uw[base + 2]);
    }
    u[j] = p * p * (1.0f / (float)DDIM);
}

// MODE 0: C = relu(A @ W^T + bias)          W is [N,K] row-major
// MODE 1: C = tanh(A @ W + bias + u)        W is [K,N] row-major
// Split-K=4 replication: serial fp32 FMA (increasing k) within each contiguous
// 512-chunk; chunk partials (kept in SMEM) combined in chunk order:
// ((p0+p1)+p2)+p3. f32x2 packs two output columns; per-element rounding chain
// is identical to the scalar version.
// Double-buffered SMEM pipeline, 2 CTAs/SM.
template <int MODE>
__global__ __launch_bounds__(256, 2) void gemm_kernel(
    const float* __restrict__ A, const float* __restrict__ W,
    const float* __restrict__ bias, const float* __restrict__ u,
    float* __restrict__ C)
{
    extern __shared__ char smem[];
    float* Abuf[2] = { (float*)(smem),
                       (float*)(smem + TILE_A_BYTES + TILE_B_BYTES) };
    float* Bbuf[2] = { (float*)(smem + TILE_A_BYTES),
                       (float*)(smem + 2 * TILE_A_BYTES + TILE_B_BYTES) };
    u64* ssum = (u64*)(smem + SMEM_SUM_OFF);

    const int tid = threadIdx.x;
    const int tx = tid & 15;         // 0..15 -> N direction (TN=8 each)
    const int ty = tid >> 4;         // 0..15 -> M direction (TM=8 each)
    const int m0 = blockIdx.y * BM;
    const int n0 = blockIdx.x * BN;

    // ---- per-thread load geometry (2 float4 per tile per operand)
    // A: idx = tid + it*256; r = idx>>2 (row in tile), c4 = idx&3 (k-group)
    const int a_r0 = tid >> 2;                 // it=0 row
    const int a_c4 = tid & 3;
    // B MODE0 same shape; MODE1: r = idx>>5 (k), c = idx&31 (n-group)
    const int b1_r0 = tid >> 5;                // it=0 k-row
    const int b1_c  = tid & 31;

    float4 ra[2], rb[2];

    // live chunk accumulator (packed column pairs)
    u64 acc2[TM][TN / 2];
#pragma unroll
    for (int i = 0; i < TM; i++)
#pragma unroll
        for (int jp = 0; jp < TN / 2; jp++) acc2[i][jp] = 0ULL;

    // ---- prologue: load tile 0, stage into buffer 0
    {
        const int k0 = 0;
#pragma unroll
        for (int it = 0; it < 2; it++) {
            int r = a_r0 + it * 64;
            ra[it] = *(const float4*)(A + (size_t)(m0 + r) * DDIM + k0 + a_c4 * 4);
        }
        if (MODE == 0) {
#pragma unroll
            for (int it = 0; it < 2; it++) {
                int r = a_r0 + it * 64;
                rb[it] = *(const float4*)(W + (size_t)(n0 + r) * DDIM + k0 + a_c4 * 4);
            }
        } else {
#pragma unroll
            for (int it = 0; it < 2; it++) {
                int r = b1_r0 + it * 8;
                rb[it] = *(const float4*)(W + (size_t)(k0 + r) * DDIM + n0 + b1_c * 4);
            }
        }
        float* As = Abuf[0];
        float* Bs = Bbuf[0];
#pragma unroll
        for (int it = 0; it < 2; it++) {
            int r = a_r0 + it * 64;
            As[(a_c4 * 4 + 0) * AS_ROW + r] = ra[it].x;
            As[(a_c4 * 4 + 1) * AS_ROW + r] = ra[it].y;
            As[(a_c4 * 4 + 2) * AS_ROW + r] = ra[it].z;
            As[(a_c4 * 4 + 3) * AS_ROW + r] = ra[it].w;
        }
        if (MODE == 0) {
#pragma unroll
            for (int it = 0; it < 2; it++) {
                int r = a_r0 + it * 64;
                Bs[(a_c4 * 4 + 0) * BS_ROW + r] = rb[it].x;
                Bs[(a_c4 * 4 + 1) * BS_ROW + r] = rb[it].y;
                Bs[(a_c4 * 4 + 2) * BS_ROW + r] = rb[it].z;
                Bs[(a_c4 * 4 + 3) * BS_ROW + r] = rb[it].w;
            }
        } else {
#pragma unroll
            for (int it = 0; it < 2; it++) {
                int r = b1_r0 + it * 8;
                *(float4*)&Bs[r * BS_ROW + b1_c * 4] = rb[it];
            }
        }
    }
    __syncthreads();

    // ---- main pipeline: one barrier per tile
#pragma unroll 1
    for (int t = 0; t < NTILES; t++) {
        const int cur = t & 1;
        const int nxt = cur ^ 1;

        // prefetch tile t+1 (GMEM -> regs), issued before compute
        if (t + 1 < NTILES) {
            const int k0 = (t + 1) * BK;
#pragma unroll
            for (int it = 0; it < 2; it++) {
                int r = a_r0 + it * 64;
                ra[it] = *(const float4*)(A + (size_t)(m0 + r) * DDIM + k0 + a_c4 * 4);
            }
            if (MODE == 0) {
#pragma unroll
                for (int it = 0; it < 2; it++) {
                    int r = a_r0 + it * 64;
                    rb[it] = *(const float4*)(W + (size_t)(n0 + r) * DDIM + k0 + a_c4 * 4);
                }
            } else {
#pragma unroll
                for (int it = 0; it < 2; it++) {
                    int r = b1_r0 + it * 8;
                    rb[it] = *(const float4*)(W + (size_t)(k0 + r) * DDIM + n0 + b1_c * 4);
                }
            }
        }

        // compute on current buffer
        {
            const float* As = Abuf[cur];
            const float* Bs = Bbuf[cur];
#pragma unroll
            for (int k = 0; k < BK; k++) {
                float a[TM];
                u64 a2[TM], b2[TN / 2];
#pragma unroll
                for (int i = 0; i < TM; i += 4)
                    *(float4*)&a[i] = *(const float4*)&As[k * AS_ROW + ty * TM + i];
#pragma unroll
                for (int i = 0; i < TM; i++)
                    PACK_F32X2_(a2[i], a[i], a[i]);
                *(ulonglong2*)&b2[0] = *(const ulonglong2*)&Bs[k * BS_ROW + tx * TN];
                *(ulonglong2*)&b2[2] = *(const ulonglong2*)&Bs[k * BS_ROW + tx * TN + 4];
#pragma unroll
                for (int i = 0; i < TM; i++)
#pragma unroll
                    for (int jp = 0; jp < TN / 2; jp++)
                        FMA_F32X2(acc2[i][jp], a2[i], b2[jp], acc2[i][jp]);
            }
        }

        // stage tile t+1 into the other buffer
        if (t + 1 < NTILES) {
            float* As = Abuf[nxt];
            float* Bs = Bbuf[nxt];
#pragma unroll
            for (int it = 0; it < 2; it++) {
                int r = a_r0 + it * 64;
                As[(a_c4 * 4 + 0) * AS_ROW + r] = ra[it].x;
                As[(a_c4 * 4 + 1) * AS_ROW + r] = ra[it].y;
                As[(a_c4 * 4 + 2) * AS_ROW + r] = ra[it].z;
                As[(a_c4 * 4 + 3) * AS_ROW + r] = ra[it].w;
            }
            if (MODE == 0) {
#pragma unroll
                for (int it = 0; it < 2; it++) {
                    int r = a_r0 + it * 64;
                    Bs[(a_c4 * 4 + 0) * BS_ROW + r] = rb[it].x;
                    Bs[(a_c4 * 4 + 1) * BS_ROW + r] = rb[it].y;
                    Bs[(a_c4 * 4 + 2) * BS_ROW + r] = rb[it].z;
                    Bs[(a_c4 * 4 + 3) * BS_ROW + r] = rb[it].w;
                }
            } else {
#pragma unroll
                for (int it = 0; it < 2; it++) {
                    int r = b1_r0 + it * 8;
                    *(float4*)&Bs[r * BS_ROW + b1_c * 4] = rb[it];
                }
            }
        }

        // chunk boundary: fold live partial into SMEM running sum
        // (store for chunk 0; read-add-store after — ((p0+p1)+p2)+p3 exactly)
        if ((t & (TILES_PER_CHUNK - 1)) == TILES_PER_CHUNK - 1) {
#pragma unroll
            for (int i = 0; i < TM; i++)
#pragma unroll
                for (int jp = 0; jp < TN / 2; jp++) {
                    int idx = (i * (TN / 2) + jp) * 256 + tid;
                    if (t == TILES_PER_CHUNK - 1) {
                        ssum[idx] = acc2[i][jp];
                    } else {
                        u64 s = ssum[idx];
                        ADD_F32X2_(s, s, acc2[i][jp]);
                        ssum[idx] = s;
                    }
                    acc2[i][jp] = 0ULL;
                }
        }

        __syncthreads();
    }

    // ---- fused epilogue (read combined sums from SMEM)
#pragma unroll
    for (int i = 0; i < TM; i++) {
        int row = m0 + ty * TM + i;
#pragma unroll
        for (int j = 0; j < TN; j += 4) {
            int col = n0 + tx * TN + j;
            int idx0 = (i * (TN / 2) + j / 2) * 256 + tid;
            int idx1 = (i * (TN / 2) + j / 2 + 1) * 256 + tid;
            float s0, s1, s2, s3;
            UNPACK_F32X2_(s0, s1, ssum[idx0]);
            UNPACK_F32X2_(s2, s3, ssum[idx1]);
            float4 v;
            v.x = s0 + bias[col + 0];
            v.y = s1 + bias[col + 1];
            v.z = s2 + bias[col + 2];
            v.w = s3 + bias[col + 3];
            if (MODE == 1) {
                v.x = tanhf(v.x + u[col + 0]);
                v.y = tanhf(v.y + u[col + 1]);
                v.z = tanhf(v.z + u[col + 2]);
                v.w = tanhf(v.w + u[col + 3]);
            } else {
                v.x = fmaxf(v.x, 0.0f);
                v.y = fmaxf(v.y, 0.0f);
                v.z = fmaxf(v.z, 0.0f);
                v.w = fmaxf(v.w, 0.0f);
            }
            *(float4*)(C + (size_t)row * DDIM + col) = v;
        }
    }
}

extern "C" void kernel_launch(void* const* d_in, const int* in_sizes, int n_in,
                              void* d_out, int out_size) {
    const float* x   = (const float*)d_in[0];
    const float* w0  = (const float*)d_in[1];
    const float* b0  = (const float*)d_in[2];
    const float* w1  = (const float*)d_in[3];
    const float* b1  = (const float*)d_in[4];
    const float* uw1 = (const float*)d_in[5];
    const float* cw1 = (const float*)d_in[6];
    const float* cb1 = (const float*)d_in[7];
    const float* w2  = (const float*)d_in[8];
    const float* b2  = (const float*)d_in[9];
    const float* uw2 = (const float*)d_in[10];
    const float* cw2 = (const float*)d_in[11];
    const float* cb2 = (const float*)d_in[12];
    const float* wf  = (const float*)d_in[13];
    const float* bf  = (const float*)d_in[14];
    float* out = (float*)d_out;

    float *buf0, *buf1, *u1, *u2;
    cudaGetSymbolAddress((void**)&buf0, g_buf0);
    cudaGetSymbolAddress((void**)&buf1, g_buf1);
    cudaGetSymbolAddress((void**)&u1, g_u1);
    cudaGetSymbolAddress((void**)&u2, g_u2);

    // opt-in to >48KB dynamic smem (idempotent; not a captured stream op)
    cudaFuncSetAttribute(gemm_kernel<0>, cudaFuncAttributeMaxDynamicSharedMemorySize, SMEM_TOTAL);
    cudaFuncSetAttribute(gemm_kernel<1>, cudaFuncAttributeMaxDynamicSharedMemorySize, SMEM_TOTAL);

    dim3 grid(DDIM / BN, DDIM / BM);
    dim3 block(256);

    // closed-form "quantum" vectors
    ultimate_u_kernel<<<DDIM / 256, 256>>>(uw1, u1);
    ultimate_u_kernel<<<DDIM / 256, 256>>>(uw2, u2);

    // 1) h = relu(x @ w0^T + b0)
    gemm_kernel<0><<<grid, block, SMEM_TOTAL>>>(x, w0, b0, nullptr, buf0);
    // 2) h = relu(h @ w1^T + b1)
    gemm_kernel<0><<<grid, block, SMEM_TOTAL>>>(buf0, w1, b1, nullptr, buf1);
    // 3) h = tanh(h @ cw1 + cb1 + u1)
    gemm_kernel<1><<<grid, block, SMEM_TOTAL>>>(buf1, cw1, cb1, u1, buf0);
    // 4) h = relu(h @ w2^T + b2)
    gemm_kernel<0><<<grid, block, SMEM_TOTAL>>>(buf0, w2, b2, nullptr, buf1);
    // 5) h = tanh(h @ cw2 + cb2 + u2)
    gemm_kernel<1><<<grid, block, SMEM_TOTAL>>>(buf1, cw2, cb2, u2, buf0);
    // 6) out = relu(h @ wf^T + bf)
    gemm_kernel<0><<<grid, block, SMEM_TOTAL>>>(buf0, wf, bf, nullptr, out);
}

// round 12
// speedup vs baseline: 1.0707x; 1.0707x over previous
#include <cuda_runtime.h>
#include <math.h>

#define DDIM 2048
#define DEPTH 9
#define BM 128
#define BN 128
#define BK 32
#define TM 8
#define TN 8
#define NCHUNK 4
#define TILES_PER_CHUNK ((DDIM / NCHUNK) / BK)   // 16
#define NTILES (DDIM / BK)                        // 64

typedef unsigned long long u64;

// Packed fp32x2 ops (Blackwell FFMA2 path). Each 32-bit lane gets IEEE fp32 .rn
// rounding identical to scalar fmaf/add — bit-exact per element. Same FLOP rate
// as scalar FFMA but half the issue slots (saves issue bandwidth + power).
#define FMA_F32X2(d, a, b, c) \
    asm("fma.rn.f32x2 %0, %1, %2, %3;" : "=l"(d) : "l"(a), "l"(b), "l"(c))
#define ADD_F32X2_(d, a, b) \
    asm("add.rn.f32x2 %0, %1, %2;" : "=l"(d) : "l"(a), "l"(b))
#define PACK_F32X2_(out, lo, hi) \
    asm("mov.b64 %0, {%1, %2};" : "=l"(out) : "f"(lo), "f"(hi))
#define UNPACK_F32X2_(lo, hi, in) \
    asm("mov.b64 {%0, %1}, %2;" : "=f"(lo), "=f"(hi) : "l"(in))

// Scratch (no allocation allowed) — ping-pong activation buffers + u vectors.
__device__ float g_buf0[(size_t)DDIM * DDIM];
__device__ float g_buf1[(size_t)DDIM * DDIM];
__device__ float g_u1[DDIM];
__device__ float g_u2[DDIM];

// u[j] = (1/n) * (prod_{d,g} cos(uw[d, j, g]))^2   (closed form of _ultimate)
// Fused: one launch computes both u1 (from uw1) and u2 (from uw2).
__global__ void ultimate_u_kernel(const float* __restrict__ uw1,
                                  const float* __restrict__ uw2,
                                  float* __restrict__ u1,
                                  float* __restrict__ u2) {
    int g = blockIdx.x * blockDim.x + threadIdx.x;
    const float* uw = (g < DDIM) ? uw1 : uw2;
    float* u        = (g < DDIM) ? u1  : u2;
    int j = (g < DDIM) ? g : g - DDIM;
    if (j >= DDIM) return;
    float p = 1.0f;
#pragma unroll
    for (int d = 0; d < DEPTH; d++) {
        size_t base = (size_t)d * DDIM * DDIM + (size_t)j * DDIM;
        p *= cosf(uw[base + 0]);
        p *= cosf(uw[base + 1]);
        p *= cosf(uw[base + 2]);
    }
    u[j] = p * p * (1.0f / (float)DDIM);
}

// MODE 0: C = relu(A @ W^T + bias)          W is [N,K] row-major
// MODE 1: C = tanh(A @ W + bias + u)        W is [K,N] row-major
// Accumulation replicates the reference's split-K=4: serial fp32 FMA
// (increasing k) within each contiguous 512-chunk; running sum += chunk
// partial at each boundary -> ((p0+p1)+p2)+p3 exactly. f32x2 packs two
// output columns per instruction; per-element rounding chain unchanged.
template <int MODE>
__global__ __launch_bounds__(256, 1) void gemm_kernel(
    const float* __restrict__ A, const float* __restrict__ W,
    const float* __restrict__ bias, const float* __restrict__ u,
    float* __restrict__ C)
{
    __shared__ float As[BK][BM + 4];
    __shared__ float Bs[BK][BN + 4];

    const int tid = threadIdx.x;
    const int tx = tid & 15;         // 0..15 -> N direction (TN=8 each)
    const int ty = tid >> 4;         // 0..15 -> M direction (TM=8 each)
    const int m0 = blockIdx.y * BM;
    const int n0 = blockIdx.x * BN;

    u64 sum2[TM][TN / 2];            // combined partials (chunk order), packed pairs
    u64 acc2[TM][TN / 2];            // live chunk accumulator, packed pairs
#pragma unroll
    for (int i = 0; i < TM; i++)
#pragma unroll
        for (int jp = 0; jp < TN / 2; jp++) { sum2[i][jp] = 0ULL; acc2[i][jp] = 0ULL; }

#pragma unroll 1
    for (int t = 0; t < NTILES; t++) {
        const int k0 = t * BK;
        // ---- load A tile: rows m0..m0+127, cols k0..k0+31, store transposed
#pragma unroll
        for (int it = 0; it < 4; it++) {
            int idx = tid + it * 256;          // 0..1023 float4 slots
            int r   = idx >> 3;                // 0..127 row within tile
            int c4  = idx & 7;                 // float4 group along k (8 groups)
            float4 v = *(const float4*)(A + (size_t)(m0 + r) * DDIM + k0 + c4 * 4);
            As[c4 * 4 + 0][r] = v.x;
            As[c4 * 4 + 1][r] = v.y;
            As[c4 * 4 + 2][r] = v.z;
            As[c4 * 4 + 3][r] = v.w;
        }
        // ---- load B tile
        if (MODE == 0) {
            // NT: W[n,k] -> transpose into Bs[k][n]
#pragma unroll
            for (int it = 0; it < 4; it++) {
                int idx = tid + it * 256;
                int r   = idx >> 3;
                int c4  = idx & 7;
                float4 v = *(const float4*)(W + (size_t)(n0 + r) * DDIM + k0 + c4 * 4);
                Bs[c4 * 4 + 0][r] = v.x;
                Bs[c4 * 4 + 1][r] = v.y;
                Bs[c4 * 4 + 2][r] = v.z;
                Bs[c4 * 4 + 3][r] = v.w;
            }
        } else {
            // NN: W[k,n] -> direct copy
#pragma unroll
            for (int it = 0; it < 4; it++) {
                int idx = tid + it * 256;      // 0..1023 float4 slots
                int r   = idx >> 5;            // 0..31 (k)
                int c4  = idx & 31;            // 0..31 (float4 group along n)
                float4 v = *(const float4*)(W + (size_t)(k0 + r) * DDIM + n0 + c4 * 4);
                *(float4*)&Bs[r][c4 * 4] = v;  // (BN+4)=132 floats/row: 16B-aligned
            }
        }
        __syncthreads();

#pragma unroll
        for (int k = 0; k < BK; k++) {
            float a[TM];
            u64 a2[TM], b2[TN / 2];
#pragma unroll
            for (int i = 0; i < TM; i += 4)
                *(float4*)&a[i] = *(const float4*)&As[k][ty * TM + i];
#pragma unroll
            for (int i = 0; i < TM; i++)
                PACK_F32X2_(a2[i], a[i], a[i]);
            // b pairs load directly as packed 64-bit lanes (16B-aligned)
            *(ulonglong2*)&b2[0] = *(const ulonglong2*)&Bs[k][tx * TN];
            *(ulonglong2*)&b2[2] = *(const ulonglong2*)&Bs[k][tx * TN + 4];
#pragma unroll
            for (int i = 0; i < TM; i++)
#pragma unroll
                for (int jp = 0; jp < TN / 2; jp++)
                    FMA_F32X2(acc2[i][jp], a2[i], b2[jp], acc2[i][jp]);
        }

        // chunk boundary: fold partial into running sum (preserves combine order)
        if ((t & (TILES_PER_CHUNK - 1)) == TILES_PER_CHUNK - 1) {
#pragma unroll
            for (int i = 0; i < TM; i++)
#pragma unroll
                for (int jp = 0; jp < TN / 2; jp++) {
                    ADD_F32X2_(sum2[i][jp], sum2[i][jp], acc2[i][jp]);
                    acc2[i][jp] = 0ULL;
                }
        }
        __syncthreads();
    }

    // ---- fused epilogue
#pragma unroll
    for (int i = 0; i < TM; i++) {
        int row = m0 + ty * TM + i;
#pragma unroll
        for (int j = 0; j < TN; j += 4) {
            int col = n0 + tx * TN + j;
            float s0, s1, s2, s3;
            UNPACK_F32X2_(s0, s1, sum2[i][j / 2]);
            UNPACK_F32X2_(s2, s3, sum2[i][j / 2 + 1]);
            float4 v;
            v.x = s0 + bias[col + 0];
            v.y = s1 + bias[col + 1];
            v.z = s2 + bias[col + 2];
            v.w = s3 + bias[col + 3];
            if (MODE == 1) {
                v.x = tanhf(v.x + u[col + 0]);
                v.y = tanhf(v.y + u[col + 1]);
                v.z = tanhf(v.z + u[col + 2]);
                v.w = tanhf(v.w + u[col + 3]);
            } else {
                v.x = fmaxf(v.x, 0.0f);
                v.y = fmaxf(v.y, 0.0f);
                v.z = fmaxf(v.z, 0.0f);
                v.w = fmaxf(v.w, 0.0f);
            }
            *(float4*)(C + (size_t)row * DDIM + col) = v;
        }
    }
}

extern "C" void kernel_launch(void* const* d_in, const int* in_sizes, int n_in,
                              void* d_out, int out_size) {
    const float* x   = (const float*)d_in[0];
    const float* w0  = (const float*)d_in[1];
    const float* b0  = (const float*)d_in[2];
    const float* w1  = (const float*)d_in[3];
    const float* b1  = (const float*)d_in[4];
    const float* uw1 = (const float*)d_in[5];
    const float* cw1 = (const float*)d_in[6];
    const float* cb1 = (const float*)d_in[7];
    const float* w2  = (const float*)d_in[8];
    const float* b2  = (const float*)d_in[9];
    const float* uw2 = (const float*)d_in[10];
    const float* cw2 = (const float*)d_in[11];
    const float* cb2 = (const float*)d_in[12];
    const float* wf  = (const float*)d_in[13];
    const float* bf  = (const float*)d_in[14];
    float* out = (float*)d_out;

    float *buf0, *buf1, *u1, *u2;
    cudaGetSymbolAddress((void**)&buf0, g_buf0);
    cudaGetSymbolAddress((void**)&buf1, g_buf1);
    cudaGetSymbolAddress((void**)&u1, g_u1);
    cudaGetSymbolAddress((void**)&u2, g_u2);

    dim3 grid(DDIM / BN, DDIM / BM);
    dim3 block(256);

    // closed-form "quantum" vectors (both in one launch)
    ultimate_u_kernel<<<2 * DDIM / 256, 256>>>(uw1, uw2, u1, u2);

    // 1) h = relu(x @ w0^T + b0)
    gemm_kernel<0><<<grid, block>>>(x, w0, b0, nullptr, buf0);
    // 2) h = relu(h @ w1^T + b1)
    gemm_kernel<0><<<grid, block>>>(buf0, w1, b1, nullptr, buf1);
    // 3) h = tanh(h @ cw1 + cb1 + u1)
    gemm_kernel<1><<<grid, block>>>(buf1, cw1, cb1, u1, buf0);
    // 4) h = relu(h @ w2^T + b2)
    gemm_kernel<0><<<grid, block>>>(buf0, w2, b2, nullptr, buf1);
    // 5) h = tanh(h @ cw2 + cb2 + u2)
    gemm_kernel<1><<<grid, block>>>(buf1, cw2, cb2, u2, buf0);
    // 6) out = relu(h @ wf^T + bf)
    gemm_kernel<0><<<grid, block>>>(buf0, wf, bf, nullptr, out);
}

// round 13
// speedup vs baseline: 1.1666x; 1.0896x over previous
#include <cuda_runtime.h>
#include <math.h>

#define DDIM 2048
#define DEPTH 9
#define BM 128
#define BN 128
#define BK 32
#define TM 8                              // rows per thread
#define TN 16                             // cols per thread
#define NTHREADS 128
#define NCHUNK 4
#define TILES_PER_CHUNK ((DDIM / NCHUNK) / BK)   // 16
#define NTILES (DDIM / BK)                        // 64

#define AS_ROW (BM + 4)                 // 132 floats
#define BS_ROW (BN + 4)                 // 132 floats
#define AS_BYTES (BK * AS_ROW * 4)      // 16896
#define BS_BYTES (BK * BS_ROW * 4)      // 16896
#define SSUM_OFF (AS_BYTES + BS_BYTES)  // 33792
#define SSUM_BYTES (NTHREADS * TM * (TN / 2) * 8)   // 65536
#define SMEM_TOTAL (SSUM_OFF + SSUM_BYTES)          // 99328

typedef unsigned long long u64;

// Packed fp32x2 ops (Blackwell FFMA2 path). Each 32-bit lane gets IEEE fp32 .rn
// rounding identical to scalar fmaf/add — bit-exact per element.
#define FMA_F32X2(d, a, b, c) \
    asm("fma.rn.f32x2 %0, %1, %2, %3;" : "=l"(d) : "l"(a), "l"(b), "l"(c))
#define ADD_F32X2_(d, a, b) \
    asm("add.rn.f32x2 %0, %1, %2;" : "=l"(d) : "l"(a), "l"(b))
#define PACK_F32X2_(out, lo, hi) \
    asm("mov.b64 %0, {%1, %2};" : "=l"(out) : "f"(lo), "f"(hi))
#define UNPACK_F32X2_(lo, hi, in) \
    asm("mov.b64 {%0, %1}, %2;" : "=f"(lo), "=f"(hi) : "l"(in))

// Conflict-free B column remap: thread tx (0..7) owns columns tx*16..tx*16+15.
// Remap puts each thread's p2-th ulonglong2 (cols tx*16+4*p2..+3) at float
// offset p2*32 + tx*4 -> lanes tx are 16B-consecutive (128B span, degree 1).
__host__ __device__ __forceinline__ int bmap(int j) {
    return ((j >> 2) & 3) * 32 + (j >> 4) * 4 + (j & 3);
}

// Scratch (no allocation allowed) — ping-pong activation buffers + u vectors.
__device__ float g_buf0[(size_t)DDIM * DDIM];
__device__ float g_buf1[(size_t)DDIM * DDIM];
__device__ float g_u1[DDIM];
__device__ float g_u2[DDIM];

// u[j] = (1/n) * (prod_{d,g} cos(uw[d, j, g]))^2   (closed form of _ultimate)
__global__ void ultimate_u_kernel(const float* __restrict__ uw1,
                                  const float* __restrict__ uw2,
                                  float* __restrict__ u1,
                                  float* __restrict__ u2) {
    int g = blockIdx.x * blockDim.x + threadIdx.x;
    const float* uw = (g < DDIM) ? uw1 : uw2;
    float* u        = (g < DDIM) ? u1  : u2;
    int j = (g < DDIM) ? g : g - DDIM;
    if (j >= DDIM) return;
    float p = 1.0f;
#pragma unroll
    for (int d = 0; d < DEPTH; d++) {
        size_t base = (size_t)d * DDIM * DDIM + (size_t)j * DDIM;
        p *= cosf(uw[base + 0]);
        p *= cosf(uw[base + 1]);
        p *= cosf(uw[base + 2]);
    }
    u[j] = p * p * (1.0f / (float)DDIM);
}

// MODE 0: C = relu(A @ W^T + bias)          W is [N,K] row-major
// MODE 1: C = tanh(A @ W + bias + u)        W is [K,N] row-major
// Accumulation replicates the reference's split-K=4: serial fp32 FMA
// (increasing k) within each contiguous 512-chunk; running sum (in SMEM,
// per-thread private) += chunk partial at each boundary -> ((p0+p1)+p2)+p3
// exactly. f32x2 packs two output columns; per-element rounding unchanged.
template <int MODE>
__global__ __launch_bounds__(NTHREADS, 2) void gemm_kernel(
    const float* __restrict__ A, const float* __restrict__ W,
    const float* __restrict__ bias, const float* __restrict__ u,
    float* __restrict__ C)
{
    extern __shared__ char smem[];
    float* As = (float*)smem;
    float* Bs = (float*)(smem + AS_BYTES);
    u64*   ssum = (u64*)(smem + SSUM_OFF);

    const int tid = threadIdx.x;
    const int tx = tid & 7;          // 0..7  -> N direction (TN=16 each)
    const int ty = tid >> 3;         // 0..15 -> M direction (TM=8 each)
    const int m0 = blockIdx.y * BM;
    const int n0 = blockIdx.x * BN;

    // load geometry (8 float4 per operand per tile)
    const int a_r0 = tid >> 3;                 // + it*16, rows 0..127
    const int a_c4 = tid & 7;                  // k-group 0..7
    const int b1_r0 = tid >> 5;                // + it*4, k rows 0..31 (MODE1)
    const int b1_c  = tid & 31;                // n-group 0..31 (MODE1)
    const int b1_f  = (b1_c & 3) * 32 + (b1_c >> 2) * 4;  // = bmap(4*b1_c)

    u64 acc2[TM][TN / 2];            // live chunk accumulator, packed col pairs
#pragma unroll
    for (int i = 0; i < TM; i++)
#pragma unroll
        for (int jp = 0; jp < TN / 2; jp++) acc2[i][jp] = 0ULL;

#pragma unroll 1
    for (int t = 0; t < NTILES; t++) {
        const int k0 = t * BK;
        // ---- A tile: rows m0..m0+127, cols k0..k0+31, transposed into As[k][m]
#pragma unroll
        for (int it = 0; it < 8; it++) {
            int r = a_r0 + it * 16;
            float4 v = *(const float4*)(A + (size_t)(m0 + r) * DDIM + k0 + a_c4 * 4);
            As[(a_c4 * 4 + 0) * AS_ROW + r] = v.x;
            As[(a_c4 * 4 + 1) * AS_ROW + r] = v.y;
            As[(a_c4 * 4 + 2) * AS_ROW + r] = v.z;
            As[(a_c4 * 4 + 3) * AS_ROW + r] = v.w;
        }
        // ---- B tile (remapped column layout)
        if (MODE == 0) {
            // NT: W[n,k] -> Bs[k][bmap(n)]
            const int f0 = bmap(a_r0);         // bmap(r0 + 16it) = f0 + 4it
#pragma unroll
            for (int it = 0; it < 8; it++) {
                int r = a_r0 + it * 16;
                int f = f0 + it * 4;
                float4 v = *(const float4*)(W + (size_t)(n0 + r) * DDIM + k0 + a_c4 * 4);
                Bs[(a_c4 * 4 + 0) * BS_ROW + f] = v.x;
                Bs[(a_c4 * 4 + 1) * BS_ROW + f] = v.y;
                Bs[(a_c4 * 4 + 2) * BS_ROW + f] = v.z;
                Bs[(a_c4 * 4 + 3) * BS_ROW + f] = v.w;
            }
        } else {
            // NN: W[k,n] -> Bs[k][bmap(n)] (float4 stays contiguous under bmap)
#pragma unroll
            for (int it = 0; it < 8; it++) {
                int r = b1_r0 + it * 4;
                float4 v = *(const float4*)(W + (size_t)(k0 + r) * DDIM + n0 + b1_c * 4);
                *(float4*)&Bs[r * BS_ROW + b1_f] = v;
            }
        }
        __syncthreads();

#pragma unroll
        for (int k = 0; k < BK; k++) {
            float a[TM];
            u64 a2[TM], b2[TN / 2];
            *(float4*)&a[0] = *(const float4*)&As[k * AS_ROW + ty * TM];
            *(float4*)&a[4] = *(const float4*)&As[k * AS_ROW + ty * TM + 4];
#pragma unroll
            for (int i = 0; i < TM; i++)
                PACK_F32X2_(a2[i], a[i], a[i]);
            // 4 conflict-free ulonglong2 loads: lanes 16B-consecutive per p2
#pragma unroll
            for (int p2 = 0; p2 < 4; p2++)
                *(ulonglong2*)&b2[p2 * 2] =
                    *(const ulonglong2*)&Bs[k * BS_ROW + p2 * 32 + tx * 4];
#pragma unroll
            for (int i = 0; i < TM; i++)
#pragma unroll
                for (int jp = 0; jp < TN / 2; jp++)
                    FMA_F32X2(acc2[i][jp], a2[i], b2[jp], acc2[i][jp]);
        }

        // chunk boundary: fold live partial into per-thread running sum in SMEM
        if ((t & (TILES_PER_CHUNK - 1)) == TILES_PER_CHUNK - 1) {
#pragma unroll
            for (int i = 0; i < TM; i++)
#pragma unroll
                for (int jp = 0; jp < TN / 2; jp++) {
                    int slot = (i * (TN / 2) + jp) * NTHREADS + tid;
                    if (t == TILES_PER_CHUNK - 1) {
                        ssum[slot] = acc2[i][jp];
                    } else {
                        u64 s = ssum[slot];
                        ADD_F32X2_(s, s, acc2[i][jp]);
                        ssum[slot] = s;
                    }
                    acc2[i][jp] = 0ULL;
                }
        }
        __syncthreads();
    }

    // ---- fused epilogue (read combined sums from SMEM)
#pragma unroll
    for (int i = 0; i < TM; i++) {
        int row = m0 + ty * TM + i;
#pragma unroll
        for (int j = 0; j < TN; j += 4) {
            int col = n0 + tx * TN + j;
            int s0i = (i * (TN / 2) + j / 2) * NTHREADS + tid;
            int s1i = (i * (TN / 2) + j / 2 + 1) * NTHREADS + tid;
            float s0, s1, s2, s3;
            UNPACK_F32X2_(s0, s1, ssum[s0i]);
            UNPACK_F32X2_(s2, s3, ssum[s1i]);
            float4 v;
            v.x = s0 + bias[col + 0];
            v.y = s1 + bias[col + 1];
            v.z = s2 + bias[col + 2];
            v.w = s3 + bias[col + 3];
            if (MODE == 1) {
                v.x = tanhf(v.x + u[col + 0]);
                v.y = tanhf(v.y + u[col + 1]);
                v.z = tanhf(v.z + u[col + 2]);
                v.w = tanhf(v.w + u[col + 3]);
            } else {
                v.x = fmaxf(v.x, 0.0f);
                v.y = fmaxf(v.y, 0.0f);
                v.z = fmaxf(v.z, 0.0f);
                v.w = fmaxf(v.w, 0.0f);
            }
            *(float4*)(C + (size_t)row * DDIM + col) = v;
        }
    }
}

extern "C" void kernel_launch(void* const* d_in, const int* in_sizes, int n_in,
                              void* d_out, int out_size) {
    const float* x   = (const float*)d_in[0];
    const float* w0  = (const float*)d_in[1];
    const float* b0  = (const float*)d_in[2];
    const float* w1  = (const float*)d_in[3];
    const float* b1  = (const float*)d_in[4];
    const float* uw1 = (const float*)d_in[5];
    const float* cw1 = (const float*)d_in[6];
    const float* cb1 = (const float*)d_in[7];
    const float* w2  = (const float*)d_in[8];
    const float* b2  = (const float*)d_in[9];
    const float* uw2 = (const float*)d_in[10];
    const float* cw2 = (const float*)d_in[11];
    const float* cb2 = (const float*)d_in[12];
    const float* wf  = (const float*)d_in[13];
    const float* bf  = (const float*)d_in[14];
    float* out = (float*)d_out;

    float *buf0, *buf1, *u1, *u2;
    cudaGetSymbolAddress((void**)&buf0, g_buf0);
    cudaGetSymbolAddress((void**)&buf1, g_buf1);
    cudaGetSymbolAddress((void**)&u1, g_u1);
    cudaGetSymbolAddress((void**)&u2, g_u2);

    // opt-in to >48KB dynamic smem (host-side attribute, not a stream op)
    cudaFuncSetAttribute(gemm_kernel<0>, cudaFuncAttributeMaxDynamicSharedMemorySize, SMEM_TOTAL);
    cudaFuncSetAttribute(gemm_kernel<1>, cudaFuncAttributeMaxDynamicSharedMemorySize, SMEM_TOTAL);

    dim3 grid(DDIM / BN, DDIM / BM);
    dim3 block(NTHREADS);

    // closed-form "quantum" vectors (both in one launch)
    ultimate_u_kernel<<<2 * DDIM / 256, 256>>>(uw1, uw2, u1, u2);

    // 1) h = relu(x @ w0^T + b0)
    gemm_kernel<0><<<grid, block, SMEM_TOTAL>>>(x, w0, b0, nullptr, buf0);
    // 2) h = relu(h @ w1^T + b1)
    gemm_kernel<0><<<grid, block, SMEM_TOTAL>>>(buf0, w1, b1, nullptr, buf1);
    // 3) h = tanh(h @ cw1 + cb1 + u1)
    gemm_kernel<1><<<grid, block, SMEM_TOTAL>>>(buf1, cw1, cb1, u1, buf0);
    // 4) h = relu(h @ w2^T + b2)
    gemm_kernel<0><<<grid, block, SMEM_TOTAL>>>(buf0, w2, b2, nullptr, buf1);
    // 5) h = tanh(h @ cw2 + cb2 + u2)
    gemm_kernel<1><<<grid, block, SMEM_TOTAL>>>(buf1, cw2, cb2, u2, buf0);
    // 6) out = relu(h @ wf^T + bf)
    gemm_kernel<0><<<grid, block, SMEM_TOTAL>>>(buf0, wf, bf, nullptr, out);
}

// round 14
// speedup vs baseline: 1.2431x; 1.0656x over previous
#include <cuda_runtime.h>
#include <math.h>

#define DDIM 2048
#define DEPTH 9
#define BM 128
#define BN 128
#define BK 32
#define TM 8
#define TN 8
#define NTHREADS 256
#define NCHUNK 4
#define TILES_PER_CHUNK ((DDIM / NCHUNK) / BK)   // 16
#define NTILES (DDIM / BK)                        // 64

#define AS_ROW (BM + 4)                 // 132 floats
#define BS_ROW (BN + 4)                 // 132 floats
#define AS_BYTES (BK * AS_ROW * 4)      // 16896
#define BS_BYTES (BK * BS_ROW * 4)      // 16896
#define SSUM_OFF (AS_BYTES + BS_BYTES)  // 33792
#define SSUM_BYTES (NTHREADS * TM * (TN / 2) * 8)   // 65536
#define SMEM_TOTAL (SSUM_OFF + SSUM_BYTES)          // 99328  (x2 CTAs = 198.7KB < 228KB)

typedef unsigned long long u64;

// Packed fp32x2 ops (Blackwell FFMA2 path). Each 32-bit lane gets IEEE fp32 .rn
// rounding identical to scalar fmaf/add — bit-exact per element; 2x the
// scalar FFMA FLOP ceiling (rt_SMSP=2 either way, double width).
#define FMA_F32X2(d, a, b, c) \
    asm("fma.rn.f32x2 %0, %1, %2, %3;" : "=l"(d) : "l"(a), "l"(b), "l"(c))
#define ADD_F32X2_(d, a, b) \
    asm("add.rn.f32x2 %0, %1, %2;" : "=l"(d) : "l"(a), "l"(b))
#define PACK_F32X2_(out, lo, hi) \
    asm("mov.b64 %0, {%1, %2};" : "=l"(out) : "f"(lo), "f"(hi))
#define UNPACK_F32X2_(lo, hi, in) \
    asm("mov.b64 {%0, %1}, %2;" : "=f"(lo), "=f"(hi) : "l"(in))

// Conflict-free B column remap for 16-wide tx, TN=8:
// col c (0..127): tx = c>>3, p2 = (c>>2)&1, w = c&3
//   f(c) = p2*64 + tx*4 + w
// Thread tx's p2-th ulonglong2 (cols tx*8+4p2 .. +3) sits at floats
// p2*64 + tx*4 -> lanes tx=0..15 are 16B-consecutive (256B span, no conflict).
// b2[jp] <-> cols (tx*8 + 2*jp, +1), same pairing as the unmapped layout.

// Scratch (no allocation allowed) — ping-pong activation buffers + u vectors.
__device__ float g_buf0[(size_t)DDIM * DDIM];
__device__ float g_buf1[(size_t)DDIM * DDIM];
__device__ float g_u1[DDIM];
__device__ float g_u2[DDIM];

// u[j] = (1/n) * (prod_{d,g} cos(uw[d, j, g]))^2   (closed form of _ultimate)
__global__ void ultimate_u_kernel(const float* __restrict__ uw1,
                                  const float* __restrict__ uw2,
                                  float* __restrict__ u1,
                                  float* __restrict__ u2) {
    int g = blockIdx.x * blockDim.x + threadIdx.x;
    const float* uw = (g < DDIM) ? uw1 : uw2;
    float* u        = (g < DDIM) ? u1  : u2;
    int j = (g < DDIM) ? g : g - DDIM;
    if (j >= DDIM) return;
    float p = 1.0f;
#pragma unroll
    for (int d = 0; d < DEPTH; d++) {
        size_t base = (size_t)d * DDIM * DDIM + (size_t)j * DDIM;
        p *= cosf(uw[base + 0]);
        p *= cosf(uw[base + 1]);
        p *= cosf(uw[base + 2]);
    }
    u[j] = p * p * (1.0f / (float)DDIM);
}

// MODE 0: C = relu(A @ W^T + bias)          W is [N,K] row-major
// MODE 1: C = tanh(A @ W + bias + u)        W is [K,N] row-major
// Accumulation replicates the reference's split-K=4: serial fp32 FMA
// (increasing k) within each contiguous 512-chunk; running sum (per-thread
// private slots in SMEM) += chunk partial at each boundary ->
// ((p0+p1)+p2)+p3 exactly. Per-element rounding chain unchanged.
template <int MODE>
__global__ __launch_bounds__(NTHREADS, 2) void gemm_kernel(
    const float* __restrict__ A, const float* __restrict__ W,
    const float* __restrict__ bias, const float* __restrict__ u,
    float* __restrict__ C)
{
    extern __shared__ char smem[];
    float* As = (float*)smem;
    float* Bs = (float*)(smem + AS_BYTES);
    u64*   ssum = (u64*)(smem + SSUM_OFF);

    const int tid = threadIdx.x;
    const int tx = tid & 15;         // 0..15 -> N direction (TN=8 each)
    const int ty = tid >> 4;         // 0..15 -> M direction (TM=8 each)
    const int m0 = blockIdx.y * BM;
    const int n0 = blockIdx.x * BN;

    // loader geometry (4 float4 per operand per tile)
    const int al_r0 = tid >> 3;                // + it*32, rows 0..127
    const int al_c4 = tid & 7;                 // k-group 0..7
    const int f0 = ((al_r0 >> 2) & 1) * 64 + (al_r0 >> 3) * 4 + (al_r0 & 3); // bmap(al_r0)
    const int bl_r0 = tid >> 5;                // + it*8, k rows 0..31 (MODE1)
    const int bl_c  = tid & 31;                // n-group 0..31 (MODE1)
    const int bl_f  = (bl_c & 1) * 64 + (bl_c >> 1) * 4;  // bmap(4*bl_c)

    u64 acc2[TM][TN / 2];            // live chunk accumulator, packed col pairs
#pragma unroll
    for (int i = 0; i < TM; i++)
#pragma unroll
        for (int jp = 0; jp < TN / 2; jp++) acc2[i][jp] = 0ULL;

#pragma unroll 1
    for (int t = 0; t < NTILES; t++) {
        const int k0 = t * BK;
        // ---- A tile: rows m0..m0+127, cols k0..k0+31 -> As[k][m] (transposed)
#pragma unroll
        for (int it = 0; it < 4; it++) {
            int r = al_r0 + it * 32;
            float4 v = *(const float4*)(A + (size_t)(m0 + r) * DDIM + k0 + al_c4 * 4);
            As[(al_c4 * 4 + 0) * AS_ROW + r] = v.x;
            As[(al_c4 * 4 + 1) * AS_ROW + r] = v.y;
            As[(al_c4 * 4 + 2) * AS_ROW + r] = v.z;
            As[(al_c4 * 4 + 3) * AS_ROW + r] = v.w;
        }
        // ---- B tile (remapped column layout)
        if (MODE == 0) {
            // NT: W[n,k] -> Bs[k][f(n)] ; f(al_r0 + 32it) = f0 + 16it
#pragma unroll
            for (int it = 0; it < 4; it++) {
                int r = al_r0 + it * 32;
                int f = f0 + it * 16;
                float4 v = *(const float4*)(W + (size_t)(n0 + r) * DDIM + k0 + al_c4 * 4);
                Bs[(al_c4 * 4 + 0) * BS_ROW + f] = v.x;
                Bs[(al_c4 * 4 + 1) * BS_ROW + f] = v.y;
                Bs[(al_c4 * 4 + 2) * BS_ROW + f] = v.z;
                Bs[(al_c4 * 4 + 3) * BS_ROW + f] = v.w;
            }
        } else {
            // NN: W[k,n] -> Bs[k][f(n)] (float4 stays contiguous under f)
#pragma unroll
            for (int it = 0; it < 4; it++) {
                int r = bl_r0 + it * 8;
                float4 v = *(const float4*)(W + (size_t)(k0 + r) * DDIM + n0 + bl_c * 4);
                *(float4*)&Bs[r * BS_ROW + bl_f] = v;
            }
        }
        __syncthreads();

#pragma unroll
        for (int k = 0; k < BK; k++) {
            float a[TM];
            u64 a2[TM], b2[TN / 2];
            *(float4*)&a[0] = *(const float4*)&As[k * AS_ROW + ty * TM];
            *(float4*)&a[4] = *(const float4*)&As[k * AS_ROW + ty * TM + 4];
#pragma unroll
            for (int i = 0; i < TM; i++)
                PACK_F32X2_(a2[i], a[i], a[i]);
            // 2 conflict-free ulonglong2 loads (lanes 16B-consecutive per p2)
            *(ulonglong2*)&b2[0] = *(const ulonglong2*)&Bs[k * BS_ROW + tx * 4];
            *(ulonglong2*)&b2[2] = *(const ulonglong2*)&Bs[k * BS_ROW + 64 + tx * 4];
#pragma unroll
            for (int i = 0; i < TM; i++)
#pragma unroll
                for (int jp = 0; jp < TN / 2; jp++)
                    FMA_F32X2(acc2[i][jp], a2[i], b2[jp], acc2[i][jp]);
        }

        // chunk boundary: fold live partial into per-thread running sum in SMEM
        if ((t & (TILES_PER_CHUNK - 1)) == TILES_PER_CHUNK - 1) {
#pragma unroll
            for (int i = 0; i < TM; i++)
#pragma unroll
                for (int jp = 0; jp < TN / 2; jp++) {
                    int slot = (i * (TN / 2) + jp) * NTHREADS + tid;
                    if (t == TILES_PER_CHUNK - 1) {
                        ssum[slot] = acc2[i][jp];
                    } else {
                        u64 s = ssum[slot];
                        ADD_F32X2_(s, s, acc2[i][jp]);
                        ssum[slot] = s;
                    }
                    acc2[i][jp] = 0ULL;
                }
        }
        __syncthreads();
    }

    // ---- fused epilogue (read combined sums from SMEM)
#pragma unroll
    for (int i = 0; i < TM; i++) {
        int row = m0 + ty * TM + i;
#pragma unroll
        for (int j = 0; j < TN; j += 4) {
            int col = n0 + tx * TN + j;
            int s0i = (i * (TN / 2) + j / 2) * NTHREADS + tid;
            int s1i = (i * (TN / 2) + j / 2 + 1) * NTHREADS + tid;
            float s0, s1, s2, s3;
            UNPACK_F32X2_(s0, s1, ssum[s0i]);
            UNPACK_F32X2_(s2, s3, ssum[s1i]);
            float4 v;
            v.x = s0 + bias[col + 0];
            v.y = s1 + bias[col + 1];
            v.z = s2 + bias[col + 2];
            v.w = s3 + bias[col + 3];
            if (MODE == 1) {
                v.x = tanhf(v.x + u[col + 0]);
                v.y = tanhf(v.y + u[col + 1]);
                v.z = tanhf(v.z + u[col + 2]);
                v.w = tanhf(v.w + u[col + 3]);
            } else {
                v.x = fmaxf(v.x, 0.0f);
                v.y = fmaxf(v.y, 0.0f);
                v.z = fmaxf(v.z, 0.0f);
                v.w = fmaxf(v.w, 0.0f);
            }
            *(float4*)(C + (size_t)row * DDIM + col) = v;
        }
    }
}

extern "C" void kernel_launch(void* const* d_in, const int* in_sizes, int n_in,
                              void* d_out, int out_size) {
    const float* x   = (const float*)d_in[0];
    const float* w0  = (const float*)d_in[1];
    const float* b0  = (const float*)d_in[2];
    const float* w1  = (const float*)d_in[3];
    const float* b1  = (const float*)d_in[4];
    const float* uw1 = (const float*)d_in[5];
    const float* cw1 = (const float*)d_in[6];
    const float* cb1 = (const float*)d_in[7];
    const float* w2  = (const float*)d_in[8];
    const float* b2  = (const float*)d_in[9];
    const float* uw2 = (const float*)d_in[10];
    const float* cw2 = (const float*)d_in[11];
    const float* cb2 = (const float*)d_in[12];
    const float* wf  = (const float*)d_in[13];
    const float* bf  = (const float*)d_in[14];
    float* out = (float*)d_out;

    float *buf0, *buf1, *u1, *u2;
    cudaGetSymbolAddress((void**)&buf0, g_buf0);
    cudaGetSymbolAddress((void**)&buf1, g_buf1);
    cudaGetSymbolAddress((void**)&u1, g_u1);
    cudaGetSymbolAddress((void**)&u2, g_u2);

    // opt-in to >48KB dynamic smem (host-side attribute, not a stream op)
    cudaFuncSetAttribute(gemm_kernel<0>, cudaFuncAttributeMaxDynamicSharedMemorySize, SMEM_TOTAL);
    cudaFuncSetAttribute(gemm_kernel<1>, cudaFuncAttributeMaxDynamicSharedMemorySize, SMEM_TOTAL);

    dim3 grid(DDIM / BN, DDIM / BM);
    dim3 block(NTHREADS);

    // closed-form "quantum" vectors (both in one launch)
    ultimate_u_kernel<<<2 * DDIM / 256, 256>>>(uw1, uw2, u1, u2);

    // 1) h = relu(x @ w0^T + b0)
    gemm_kernel<0><<<grid, block, SMEM_TOTAL>>>(x, w0, b0, nullptr, buf0);
    // 2) h = relu(h @ w1^T + b1)
    gemm_kernel<0><<<grid, block, SMEM_TOTAL>>>(buf0, w1, b1, nullptr, buf1);
    // 3) h = tanh(h @ cw1 + cb1 + u1)
    gemm_kernel<1><<<grid, block, SMEM_TOTAL>>>(buf1, cw1, cb1, u1, buf0);
    // 4) h = relu(h @ w2^T + b2)
    gemm_kernel<0><<<grid, block, SMEM_TOTAL>>>(buf0, w2, b2, nullptr, buf1);
    // 5) h = tanh(h @ cw2 + cb2 + u2)
    gemm_kernel<1><<<grid, block, SMEM_TOTAL>>>(buf1, cw2, cb2, u2, buf0);
    // 6) out = relu(h @ wf^T + bf)
    gemm_kernel<0><<<grid, block, SMEM_TOTAL>>>(buf0, wf, bf, nullptr, out);
}